// round 5
// baseline (speedup 1.0000x reference)
#include <cuda_runtime.h>

#define HH 56
#define WW 56
#define CHW (HH * WW)     // 3136
#define CHW4 (CHW / 4)    // 784
#define NCH 16            // c-chunks (4 channels each)

// grid = 224: bid = h*4 + p. block = 448 threads.
__global__ __launch_bounds__(448)
void fused_shuffle_conv(const float* __restrict__ x,   // [128,56,56]
                        const float* __restrict__ w0,  // [32,2,3,3]
                        const float* __restrict__ w1,  // [4,64]
                        float* __restrict__ out)       // [128,56,56]
{
    __shared__ float4 t4part[NCH][2][14];   // [chunk][g][w4]  7168 B
    __shared__ float  t4s[2][WW + 4];       // [g][w+2], zero pad 2 each side
    __shared__ float  W5s[32][2][5];        // collapsed 5-tap kernel

    const int bid = blockIdx.x;
    const int h   = bid >> 2;
    const int p   = bid & 3;
    const int tid = threadIdx.x;

    // ---- Phase B: each thread: 4 LDG.128 (independent -> 1 latency round), 16 FFMA.
    //      chunk = tid/28 covers c in [4*chunk, 4*chunk+4); r = tid%28 -> (g, w4)
    {
        const int chunk = tid / 28;
        const int r     = tid % 28;
        const int g     = r / 14;
        const int w4    = r % 14;

        const float4* x4 = (const float4*)x;
        const int rowoff = h * 14 + w4;

        float4 v[4];
        #pragma unroll
        for (int c = 0; c < 4; c++) {
            int cc = chunk * 4 + c;
            v[c] = x4[(size_t)(2 * cc + g) * CHW4 + rowoff];
        }

        float4 acc = make_float4(0.f, 0.f, 0.f, 0.f);
        #pragma unroll
        for (int c = 0; c < 4; c++) {
            float wv = __ldg(w1 + p * 64 + chunk * 4 + c);
            acc.x += v[c].x * wv;
            acc.y += v[c].y * wv;
            acc.z += v[c].z * wv;
            acc.w += v[c].w * wv;
        }
        t4part[chunk][g][w4] = acc;
    }

    // ---- W5[l][g][d] = sum_{u1+u2=d} w0[l,g,u1,u2]  (320 entries, one pass) ----
    if (tid < 320) {
        int l = tid / 10;
        int r = tid % 10;
        int g = r / 5, d = r % 5;
        const float* w0lg = w0 + (l * 2 + g) * 9;
        float s = 0.f;
        #pragma unroll
        for (int u1 = 0; u1 < 3; u1++) {
            int u2 = d - u1;
            if (u2 >= 0 && u2 < 3) s += w0lg[u1 * 3 + u2];
        }
        W5s[l][g][d] = s;
    }

    // ---- zero t4s W-padding (positions 0,1,58,59 per g) ----
    if (tid >= 440 && tid < 448) {
        int e = tid - 440;          // 0..7
        int g = e >> 2, k = e & 3;
        t4s[g][(k < 2) ? k : (WW + k)] = 0.f;
    }

    __syncthreads();

    // ---- combine 16 chunk-partials: 112 threads, 16 conflict-free LDS each ----
    if (tid < 2 * WW) {
        const int g = tid / WW, w = tid % WW;
        const float* tp = &(((const float*)t4part)[g * 56 + (w / 4) * 4 + (w % 4)]);
        float s = 0.f;
        #pragma unroll
        for (int ch = 0; ch < NCH; ch++)
            s += tp[ch * 112];
        t4s[g][w + 2] = s;
    }

    __syncthreads();

    // ---- Phase C: 5-tap conv + boundary corrections + H-roll ----
    // 448 threads: w = tid%56, q = tid/56 in [0,8); thread handles l = q+8*li, li in [0,4)
    {
        const int w = tid % WW;
        const int q = tid / WW;
        const int hout = (h + 1) % HH;

        float t4r[2][5];
        #pragma unroll
        for (int g = 0; g < 2; g++)
            #pragma unroll
            for (int d = 0; d < 5; d++)
                t4r[g][d] = t4s[g][w + d];

        const bool bl = (w == 0);
        const bool br = (w == WW - 1);

        #pragma unroll
        for (int li = 0; li < 4; li++) {
            const int l = q + li * 8;
            float acc = 0.f;
            #pragma unroll
            for (int g = 0; g < 2; g++)
                #pragma unroll
                for (int d = 0; d < 5; d++)
                    acc += W5s[l][g][d] * t4r[g][d];

            // boundary corrections (mask on u2 of the second unfold):
            //   w==0 : -w0[l,g,2,0]*t4[g,0];  w==55 : -w0[l,g,0,2]*t4[g,55]
            if (bl | br) {
                int off = bl ? 6 : 2;
                float cg0 = __ldg(w0 + (l * 2 + 0) * 9 + off);
                float cg1 = __ldg(w0 + (l * 2 + 1) * 9 + off);
                acc -= cg0 * t4r[0][2] + cg1 * t4r[1][2];
            }
            out[(size_t)(l * 4 + p) * CHW + (size_t)hout * WW + w] = acc;
        }
    }
}

extern "C" void kernel_launch(void* const* d_in, const int* in_sizes, int n_in,
                              void* d_out, int out_size)
{
    const float* x  = (const float*)d_in[0];   // [1,128,56,56]
    const float* w0 = (const float*)d_in[1];   // [32,2,3,3]
    const float* w1 = (const float*)d_in[2];   // [4,64]
    float* out = (float*)d_out;                // [1,128,56,56]

    fused_shuffle_conv<<<HH * 4, 448>>>(x, w0, w1, out);
}

// round 6
// speedup vs baseline: 1.0821x; 1.0821x over previous
#include <cuda_runtime.h>

#define HH 56
#define WW 56
#define CHW (HH * WW)     // 3136
#define CHW4 (CHW / 4)    // 784
#define NCH 16            // c-chunks (4 channels each)

// grid = 112: bid = h*2 + ph; block covers p = {2*ph, 2*ph+1}. block = 448 threads.
__global__ __launch_bounds__(448)
void fused_shuffle_conv(const float* __restrict__ x,   // [128,56,56]
                        const float* __restrict__ w0,  // [32,2,3,3]
                        const float* __restrict__ w1,  // [4,64]
                        float* __restrict__ out)       // [128,56,56]
{
    __shared__ float4 t4part[NCH][2][2][14]; // [chunk][p_local][g][w4]  14336 B
    __shared__ float  t4s[2][2][WW + 4];     // [p_local][g][w+2], zero pad 2 each side
    __shared__ float  W5s[32][2][5];         // collapsed 5-tap kernel

    const int bid = blockIdx.x;
    const int h   = bid >> 1;
    const int ph  = bid & 1;            // p = 2*ph + p_local
    const int tid = threadIdx.x;

    // ---- Phase B: 4 independent LDG.128 (one latency round), 32 FFMA, 2 p-accumulators.
    //      tid -> chunk (16) x g (2) x w4 (14); chunk covers c in [4*chunk, 4*chunk+4)
    {
        const int chunk = tid / 28;
        const int r     = tid % 28;
        const int g     = r / 14;
        const int w4    = r % 14;

        const float4* x4 = (const float4*)x;
        const int rowoff = h * 14 + w4;

        float4 v[4];
        #pragma unroll
        for (int c = 0; c < 4; c++) {
            int cc = chunk * 4 + c;
            v[c] = x4[(size_t)(2 * cc + g) * CHW4 + rowoff];
        }

        float4 acc0 = make_float4(0.f, 0.f, 0.f, 0.f);
        float4 acc1 = make_float4(0.f, 0.f, 0.f, 0.f);
        #pragma unroll
        for (int c = 0; c < 4; c++) {
            float wv0 = __ldg(w1 + (2 * ph + 0) * 64 + chunk * 4 + c);
            float wv1 = __ldg(w1 + (2 * ph + 1) * 64 + chunk * 4 + c);
            acc0.x += v[c].x * wv0;  acc0.y += v[c].y * wv0;
            acc0.z += v[c].z * wv0;  acc0.w += v[c].w * wv0;
            acc1.x += v[c].x * wv1;  acc1.y += v[c].y * wv1;
            acc1.z += v[c].z * wv1;  acc1.w += v[c].w * wv1;
        }
        t4part[chunk][0][g][w4] = acc0;
        t4part[chunk][1][g][w4] = acc1;
    }

    // ---- W5[l][g][d] = sum_{u1+u2=d} w0[l,g,u1,u2]  (320 entries, one pass) ----
    if (tid < 320) {
        int l = tid / 10;
        int r = tid % 10;
        int g = r / 5, d = r % 5;
        const float* w0lg = w0 + (l * 2 + g) * 9;
        float s = 0.f;
        #pragma unroll
        for (int u1 = 0; u1 < 3; u1++) {
            int u2 = d - u1;
            if (u2 >= 0 && u2 < 3) s += w0lg[u1 * 3 + u2];
        }
        W5s[l][g][d] = s;
    }

    // ---- zero t4s W-padding (positions 0,1,58,59 per (p_local,g)) ----
    if (tid >= 432 && tid < 448) {
        int e  = tid - 432;            // 0..15
        int pl = e >> 3, g = (e >> 2) & 1, k = e & 3;
        t4s[pl][g][(k < 2) ? k : (WW + k)] = 0.f;
    }

    __syncthreads();

    // ---- combine 16 chunk-partials: 224 threads, conflict-free
    //      (chunk stride = 224 floats = 7*32 -> same-bank offset, lanes walk w) ----
    if (tid < 2 * 2 * WW) {
        const int pl = tid / 112;
        const int g  = (tid / WW) % 2;
        const int w  = tid % WW;
        const float* tp = ((const float*)t4part) + pl * 112 + g * 56 + w;
        float s = 0.f;
        #pragma unroll
        for (int ch = 0; ch < NCH; ch++)
            s += tp[ch * 224];
        t4s[pl][g][w + 2] = s;
    }

    __syncthreads();

    // ---- Phase C: 5-tap conv + boundary corrections + H-roll ----
    // 448 threads: w = tid%56, q = tid/56 in [0,8): p_local = q&1, l = (q>>1) + 4*li, li<8
    {
        const int w  = tid % WW;
        const int q  = tid / WW;
        const int pl = q & 1;
        const int lq = q >> 1;
        const int p  = 2 * ph + pl;
        const int hout = (h + 1) % HH;

        float t4r[2][5];
        #pragma unroll
        for (int g = 0; g < 2; g++)
            #pragma unroll
            for (int d = 0; d < 5; d++)
                t4r[g][d] = t4s[pl][g][w + d];

        const bool bl = (w == 0);
        const bool br = (w == WW - 1);

        #pragma unroll
        for (int li = 0; li < 8; li++) {
            const int l = lq + li * 4;
            float acc = 0.f;
            #pragma unroll
            for (int g = 0; g < 2; g++)
                #pragma unroll
                for (int d = 0; d < 5; d++)
                    acc += W5s[l][g][d] * t4r[g][d];

            // boundary corrections (mask on u2 of the second unfold):
            //   w==0 : -w0[l,g,2,0]*t4[g,0];  w==55 : -w0[l,g,0,2]*t4[g,55]
            if (bl | br) {
                int off = bl ? 6 : 2;
                float cg0 = __ldg(w0 + (l * 2 + 0) * 9 + off);
                float cg1 = __ldg(w0 + (l * 2 + 1) * 9 + off);
                acc -= cg0 * t4r[0][2] + cg1 * t4r[1][2];
            }
            out[(size_t)(l * 4 + p) * CHW + (size_t)hout * WW + w] = acc;
        }
    }
}

extern "C" void kernel_launch(void* const* d_in, const int* in_sizes, int n_in,
                              void* d_out, int out_size)
{
    const float* x  = (const float*)d_in[0];   // [1,128,56,56]
    const float* w0 = (const float*)d_in[1];   // [32,2,3,3]
    const float* w1 = (const float*)d_in[2];   // [4,64]
    float* out = (float*)d_out;                // [1,128,56,56]

    fused_shuffle_conv<<<HH * 2, 448>>>(x, w0, w1, out);
}